// round 10
// baseline (speedup 1.0000x reference)
#include <cuda_runtime.h>
#include <cstdint>

#define B_ 16
#define C_ 256
#define H_ 56
#define W_ 56
#define G_ 4
#define PAD_ 5
#define PH_ 66
#define PW_ 66
#define TW_ 8

// Scratch (static device globals — no allocation at runtime).
__device__ ulonglong2 g_pk[B_ * PH_ * PW_ * G_];          // (sign, nonzero) per (b,py,px,g)
__device__ unsigned long long g_wbits[3][9][C_];          // weight sign bits [branch][tap][outch]
__device__ float g_params[3][4][C_];                      // [branch][{scale, cb-move1, alpha, move2}][outch]

// ---- single-LOP3 helpers ----
__device__ __forceinline__ uint32_t lop3_xor3(uint32_t a, uint32_t b, uint32_t c) { // a^b^c
    uint32_t r; asm("lop3.b32 %0, %1, %2, %3, 0x96;" : "=r"(r) : "r"(a), "r"(b), "r"(c)); return r;
}
__device__ __forceinline__ uint32_t lop3_maj(uint32_t a, uint32_t b, uint32_t c) {  // majority
    uint32_t r; asm("lop3.b32 %0, %1, %2, %3, 0xE8;" : "=r"(r) : "r"(a), "r"(b), "r"(c)); return r;
}
__device__ __forceinline__ uint32_t lop3_mask(uint32_t nz, uint32_t s, uint32_t w) { // nz & (s^w)
    uint32_t r; asm("lop3.b32 %0, %1, %2, %3, 0x60;" : "=r"(r) : "r"(nz), "r"(s), "r"(w)); return r;
}

// ---------------------------------------------------------------------------
// Pack activations (coalesced): warp = one group, lanes = consecutive x.
// Grid split in 2 x-halves for 2x block-level parallelism (DRAM util).
// ---------------------------------------------------------------------------
__global__ void pack_kernel(const float* __restrict__ x, const float* __restrict__ bias) {
    const int half = blockIdx.x;           // 0: px 0..32, 1: px 33..65
    const int py   = blockIdx.y;
    const int b    = blockIdx.z;
    const int g    = threadIdx.x >> 5;     // 4 warps = 4 groups
    const int lane = threadIdx.x & 31;
    const int yy   = py - PAD_;
    const bool rowin = (yy >= 0) && (yy < H_);
    const float* bp = bias + g * 64;
    const int pxEnd = half * 33 + 33;

    #pragma unroll
    for (int j = 0; j < 2; j++) {
        int px = half * 33 + j * 32 + lane;
        if (px >= pxEnd || px >= PW_) continue;
        int xx = px - PAD_;
        bool in = rowin && (xx >= 0) && (xx < W_);
        unsigned long long s = 0ull, nz = 0ull;
        if (in) {
            const float* xp = x + (((size_t)b * C_ + g * 64) * H_ + yy) * W_ + xx;
            #pragma unroll
            for (int c = 0; c < 64; c++) {
                float v = __ldg(xp + (size_t)c * (H_ * W_)) + __ldg(bp + c);
                s  |= (unsigned long long)(v > 0.0f)  << c;
                nz |= (unsigned long long)(v != 0.0f) << c;
            }
        }
        g_pk[(((size_t)b * PH_ + py) * PW_ + px) * G_ + g] = make_ulonglong2(s, nz);
    }
}

// ---------------------------------------------------------------------------
// Weight prep: per (branch, outch): mean|w|, sign bits per tap, fused params.
// ---------------------------------------------------------------------------
__global__ void wprep_kernel(const float* __restrict__ w, const float* __restrict__ cb,
                             const float* __restrict__ mv1, const float* __restrict__ alpha,
                             const float* __restrict__ mv2) {
    int o  = blockIdx.x;   // 0..255
    int br = blockIdx.y;   // 0..2
    int c  = threadIdx.x;  // 0..63
    const float* wp = w + (((size_t)br * C_ + o) * 64 + c) * 9;
    float vals[9];
    float sum = 0.0f, asum = 0.0f;
    #pragma unroll
    for (int t = 0; t < 9; t++) { float v = wp[t]; vals[t] = v; sum += v; asum += fabsf(v); }

    __shared__ float s1[64], s2[64];
    s1[c] = sum; s2[c] = asum;
    __syncthreads();
    #pragma unroll
    for (int off = 32; off > 0; off >>= 1) {
        if (c < off) { s1[c] += s1[c + off]; s2[c] += s2[c + off]; }
        __syncthreads();
    }
    float mean = s1[0] * (1.0f / 576.0f);

    __shared__ unsigned int bits[9][2];
    #pragma unroll
    for (int t = 0; t < 9; t++) {
        unsigned bm = __ballot_sync(0xFFFFFFFFu, vals[t] > mean);
        if ((c & 31) == 0) bits[t][c >> 5] = bm;
    }
    __syncthreads();
    if (c < 9)
        g_wbits[br][c][o] = ((unsigned long long)bits[c][1] << 32) | (unsigned long long)bits[c][0];
    if (c == 0) {
        int i = br * C_ + o;
        g_params[br][0][o] = s2[0] * (1.0f / 576.0f);   // scale = mean|w|
        g_params[br][1][o] = cb[i] - mv1[i];            // fused conv-bias - move1
        g_params[br][2][o] = alpha[i];
        g_params[br][3][o] = mv2[i];
    }
}

// ---------------------------------------------------------------------------
// Main kernel: one block = (b, y, 8 x), 256 threads = 256 out channels.
// XNOR conv, row-wise CSA popcount, fused RPReLU + sum + channel LayerNorm.
// Smem union (tile/redbuf) + tight register lifetimes -> occupancy 3.
// ---------------------------------------------------------------------------
__global__ void __launch_bounds__(256, 3)
main_kernel(const float* __restrict__ gamma, const float* __restrict__ beta,
            float* __restrict__ out) {
    const int x0 = blockIdx.x * TW_;
    const int y  = blockIdx.y;
    const int b  = blockIdx.z;
    const int o  = threadIdx.x;
    const int g  = o >> 6;

    // union: conv phase uses tile[7*18*4] uint4 (8064B); LN phase uses redbuf[8][256] floats (8192B)
    __shared__ __align__(16) char smbuf[8192];
    uint4* tile   = (uint4*)smbuf;
    float (*redbuf)[256] = (float (*)[256])smbuf;
    __shared__ int pzs[3][4][TW_];
    __shared__ float stats[TW_][2];

    // ---- load tile ----
    const int rowoff[7] = {-5, -3, -1, 0, 1, 3, 5};
    for (int e = o; e < 7 * 18 * 4; e += 256) {
        int gg  = e & 3;
        int q   = e >> 2;
        int col = q % 18;
        int r   = q / 18;
        int py  = y + rowoff[r] + PAD_;
        int px  = x0 + col;
        tile[e] = ((const uint4*)g_pk)[(((size_t)b * PH_ + py) * PW_ + px) * G_ + gg];
    }
    __syncthreads();

    // ---- per-(branch,group,x) sum of popc(nz) over 9 taps ----
    if (o < 96) {
        int br = o / 32, rem = o % 32;
        int gg = rem >> 3, p = rem & 7;
        int d = 2 * br + 1;
        int s = 0;
        #pragma unroll
        for (int ky = 0; ky < 3; ky++) {
            int ridx = 3 + (ky - 1) * (br + 1);
            #pragma unroll
            for (int kx = 0; kx < 3; kx++) {
                int col = 5 + p + (kx - 1) * d;
                const uint4 v = tile[(ridx * 18 + col) * 4 + gg];
                s += __popc(v.z) + __popc(v.w);
            }
        }
        pzs[br][gg][p] = s;
    }
    __syncthreads();

    // ---- XNOR conv with row-wise CSA popcount, 3 branches, fused RPReLU ----
    float outv[TW_];
    {
        float m2s = g_params[0][3][o] + g_params[1][3][o] + g_params[2][3][o];
        #pragma unroll
        for (int p = 0; p < TW_; p++) outv[p] = m2s;
    }

    const uint4* tg = tile + g;

    #pragma unroll
    for (int br = 0; br < 3; br++) {
        const int d = 2 * br + 1;
        const int rstep = br + 1;
        uint32_t wlo[9], whi[9];
        #pragma unroll
        for (int t = 0; t < 9; t++) {
            unsigned long long wq = g_wbits[br][t][o];
            wlo[t] = (uint32_t)wq;
            whi[t] = (uint32_t)(wq >> 32);
        }
        const float scl = g_params[br][0][o];
        const float c0  = g_params[br][1][o];
        const float al  = g_params[br][2][o];
        #pragma unroll
        for (int p = 0; p < TW_; p++) {
            // row-wise: masks die immediately into level-1 FA outputs
            uint32_t sl[3], cl[3], sh[3], ch[3];
            #pragma unroll
            for (int ky = 0; ky < 3; ky++) {
                const int ridx = 3 + (ky - 1) * rstep;
                const uint4 v0 = tg[(ridx * 18 + 5 + p - d) * 4];
                const uint4 v1 = tg[(ridx * 18 + 5 + p) * 4];
                const uint4 v2 = tg[(ridx * 18 + 5 + p + d) * 4];
                uint32_t a0 = lop3_mask(v0.z, v0.x, wlo[ky * 3 + 0]);
                uint32_t a1 = lop3_mask(v1.z, v1.x, wlo[ky * 3 + 1]);
                uint32_t a2 = lop3_mask(v2.z, v2.x, wlo[ky * 3 + 2]);
                sl[ky] = lop3_xor3(a0, a1, a2);
                cl[ky] = lop3_maj(a0, a1, a2);
                uint32_t b0 = lop3_mask(v0.w, v0.y, whi[ky * 3 + 0]);
                uint32_t b1 = lop3_mask(v1.w, v1.y, whi[ky * 3 + 1]);
                uint32_t b2 = lop3_mask(v2.w, v2.y, whi[ky * 3 + 2]);
                sh[ky] = lop3_xor3(b0, b1, b2);
                ch[ky] = lop3_maj(b0, b1, b2);
            }
            // level 2 + weighted popcount
            uint32_t Sl  = lop3_xor3(sl[0], sl[1], sl[2]), C2la = lop3_maj(sl[0], sl[1], sl[2]);
            uint32_t S2l = lop3_xor3(cl[0], cl[1], cl[2]), C4l  = lop3_maj(cl[0], cl[1], cl[2]);
            uint32_t Sh  = lop3_xor3(sh[0], sh[1], sh[2]), C2ha = lop3_maj(sh[0], sh[1], sh[2]);
            uint32_t S2h = lop3_xor3(ch[0], ch[1], ch[2]), C4h  = lop3_maj(ch[0], ch[1], ch[2]);
            int w1 = __popc(Sl) + __popc(Sh);
            int w2 = __popc(C2la) + __popc(S2l) + __popc(C2ha) + __popc(S2h);
            int w4 = __popc(C4l) + __popc(C4h);
            int dsum = w1 + 2 * w2 + 4 * w4;
            int dot  = pzs[br][g][p] - 2 * dsum;   // integer-exact +/-1 dot product
            float yv = scl * (float)dot + c0;
            yv = (yv >= 0.0f) ? yv : al * yv;      // RPReLU core
            outv[p] += yv;
        }
    }

    // ---- fused LayerNorm over channels (smem reused: tile -> redbuf) ----
    __syncthreads();   // all tile reads complete before overwrite
    #pragma unroll
    for (int p = 0; p < TW_; p++) redbuf[p][o] = outv[p];
    __syncthreads();
    {
        int wid = o >> 5, lane = o & 31;  // 8 warps, warp w reduces position w
        float s = 0.0f, sq = 0.0f;
        #pragma unroll
        for (int k = 0; k < 8; k++) {
            float v = redbuf[wid][lane + 32 * k];
            s += v; sq += v * v;
        }
        #pragma unroll
        for (int off = 16; off > 0; off >>= 1) {
            s  += __shfl_down_sync(0xFFFFFFFFu, s,  off);
            sq += __shfl_down_sync(0xFFFFFFFFu, sq, off);
        }
        if (lane == 0) {
            float mean = s * (1.0f / 256.0f);
            float var  = sq * (1.0f / 256.0f) - mean * mean;
            stats[wid][0] = mean;
            stats[wid][1] = rsqrtf(var + 1e-5f);
        }
    }
    __syncthreads();

    float gm = gamma[o], bt = beta[o];
    float res[TW_];
    #pragma unroll
    for (int p = 0; p < TW_; p++)
        res[p] = (outv[p] - stats[p][0]) * stats[p][1] * gm + bt;

    float4* op = (float4*)(out + (((size_t)b * C_ + o) * H_ + y) * W_ + x0);
    op[0] = make_float4(res[0], res[1], res[2], res[3]);
    op[1] = make_float4(res[4], res[5], res[6], res[7]);
}

// ---------------------------------------------------------------------------
extern "C" void kernel_launch(void* const* d_in, const int* in_sizes, int n_in,
                              void* d_out, int out_size) {
    const float* x     = (const float*)d_in[0];
    const float* bias  = (const float*)d_in[1];
    const float* w     = (const float*)d_in[2];
    const float* cb    = (const float*)d_in[3];
    const float* mv1   = (const float*)d_in[4];
    const float* alpha = (const float*)d_in[5];
    const float* mv2   = (const float*)d_in[6];
    const float* gamma = (const float*)d_in[7];
    const float* beta  = (const float*)d_in[8];
    float* out = (float*)d_out;

    pack_kernel<<<dim3(2, PH_, B_), 128>>>(x, bias);
    wprep_kernel<<<dim3(C_, 3), 64>>>(w, cb, mv1, alpha, mv2);
    main_kernel<<<dim3(W_ / TW_, H_, B_), 256>>>(gamma, beta, out);
}

// round 11
// speedup vs baseline: 1.9724x; 1.9724x over previous
#include <cuda_runtime.h>
#include <cstdint>

#define B_ 16
#define C_ 256
#define H_ 56
#define W_ 56
#define G_ 4
#define PAD_ 5
#define PH_ 66
#define PW_ 66
#define TW_ 8

// Scratch (static device globals — no allocation at runtime).
__device__ ulonglong2 g_pk[B_ * PH_ * PW_ * G_];          // (sign, nonzero) per (b,py,px,g)
__device__ unsigned long long g_wbits[3][9][C_];          // weight sign bits [branch][tap][outch]
__device__ float g_params[3][4][C_];                      // [branch][{scale, cb-move1, alpha, move2}][outch]

__device__ __forceinline__ uint32_t lop3_mask(uint32_t nz, uint32_t s, uint32_t w) { // nz & (s^w)
    uint32_t r; asm("lop3.b32 %0, %1, %2, %3, 0x60;" : "=r"(r) : "r"(nz), "r"(s), "r"(w)); return r;
}
// acc += -2 * v on the FMA pipe (IMAD), keeping the ALU pipe free for LOP3/POPC
__device__ __forceinline__ void imad_m2(int& acc, int v) {
    asm("mad.lo.s32 %0, %1, -2, %0;" : "+r"(acc) : "r"(v));
}

// ---------------------------------------------------------------------------
// Pack activations (coalesced, R9 version): warp = one group, lanes = consec x.
// ---------------------------------------------------------------------------
__global__ void pack_kernel(const float* __restrict__ x, const float* __restrict__ bias) {
    const int py   = blockIdx.x;
    const int b    = blockIdx.y;
    const int g    = threadIdx.x >> 5;     // 4 warps = 4 groups
    const int lane = threadIdx.x & 31;
    const int yy   = py - PAD_;
    const bool rowin = (yy >= 0) && (yy < H_);
    const float* bp = bias + g * 64;

    #pragma unroll
    for (int px0 = 0; px0 < PW_; px0 += 32) {
        int px = px0 + lane;
        int xx = px - PAD_;
        bool in = rowin && (xx >= 0) && (xx < W_) && (px < PW_);
        unsigned long long s = 0ull, nz = 0ull;
        if (in) {
            const float* xp = x + (((size_t)b * C_ + g * 64) * H_ + yy) * W_ + xx;
            #pragma unroll
            for (int c = 0; c < 64; c++) {
                float v = __ldg(xp + (size_t)c * (H_ * W_)) + __ldg(bp + c);
                s  |= (unsigned long long)(v > 0.0f)  << c;
                nz |= (unsigned long long)(v != 0.0f) << c;
            }
        }
        if (px < PW_)
            g_pk[(((size_t)b * PH_ + py) * PW_ + px) * G_ + g] = make_ulonglong2(s, nz);
    }
}

// ---------------------------------------------------------------------------
// Weight prep: per (branch, outch): mean|w|, sign bits per tap, fused params.
// ---------------------------------------------------------------------------
__global__ void wprep_kernel(const float* __restrict__ w, const float* __restrict__ cb,
                             const float* __restrict__ mv1, const float* __restrict__ alpha,
                             const float* __restrict__ mv2) {
    int o  = blockIdx.x;   // 0..255
    int br = blockIdx.y;   // 0..2
    int c  = threadIdx.x;  // 0..63
    const float* wp = w + (((size_t)br * C_ + o) * 64 + c) * 9;
    float vals[9];
    float sum = 0.0f, asum = 0.0f;
    #pragma unroll
    for (int t = 0; t < 9; t++) { float v = wp[t]; vals[t] = v; sum += v; asum += fabsf(v); }

    __shared__ float s1[64], s2[64];
    s1[c] = sum; s2[c] = asum;
    __syncthreads();
    #pragma unroll
    for (int off = 32; off > 0; off >>= 1) {
        if (c < off) { s1[c] += s1[c + off]; s2[c] += s2[c + off]; }
        __syncthreads();
    }
    float mean = s1[0] * (1.0f / 576.0f);

    __shared__ unsigned int bits[9][2];
    #pragma unroll
    for (int t = 0; t < 9; t++) {
        unsigned bm = __ballot_sync(0xFFFFFFFFu, vals[t] > mean);
        if ((c & 31) == 0) bits[t][c >> 5] = bm;
    }
    __syncthreads();
    if (c < 9)
        g_wbits[br][c][o] = ((unsigned long long)bits[c][1] << 32) | (unsigned long long)bits[c][0];
    if (c == 0) {
        int i = br * C_ + o;
        g_params[br][0][o] = s2[0] * (1.0f / 576.0f);   // scale = mean|w|
        g_params[br][1][o] = cb[i] - mv1[i];            // fused conv-bias - move1
        g_params[br][2][o] = alpha[i];
        g_params[br][3][o] = mv2[i];
    }
}

// ---------------------------------------------------------------------------
// Main kernel: one block = (b, y, 8 x), 256 threads = 256 out channels.
// XNOR conv: mask (LOP3, alu) -> POPC (alu) -> IMAD -2 accumulate (fma pipe).
// Fused RPReLU + branch sum + channel LayerNorm. Occupancy 2.
// ---------------------------------------------------------------------------
__global__ void __launch_bounds__(256, 2)
main_kernel(const float* __restrict__ gamma, const float* __restrict__ beta,
            float* __restrict__ out) {
    const int x0 = blockIdx.x * TW_;
    const int y  = blockIdx.y;
    const int b  = blockIdx.z;
    const int o  = threadIdx.x;
    const int g  = o >> 6;

    __shared__ uint4 tile[7 * 18 * 4];   // {s_lo, s_hi, nz_lo, nz_hi} per (row,col,group)
    __shared__ int pzs[3][4][TW_];       // sum of popc(nz) over 9 taps
    __shared__ float redbuf[TW_][256];
    __shared__ float stats[TW_][2];

    // ---- load tile ----
    const int rowoff[7] = {-5, -3, -1, 0, 1, 3, 5};
    for (int e = o; e < 7 * 18 * 4; e += 256) {
        int gg  = e & 3;
        int q   = e >> 2;
        int col = q % 18;
        int r   = q / 18;
        int py  = y + rowoff[r] + PAD_;
        int px  = x0 + col;
        tile[e] = ((const uint4*)g_pk)[(((size_t)b * PH_ + py) * PW_ + px) * G_ + gg];
    }
    __syncthreads();

    // ---- per-(branch,group,x) sum of popc(nz) over 9 taps ----
    if (o < 96) {
        int br = o / 32, rem = o % 32;
        int gg = rem >> 3, p = rem & 7;
        int d = 2 * br + 1;
        int s = 0;
        #pragma unroll
        for (int ky = 0; ky < 3; ky++) {
            int ridx = 3 + (ky - 1) * (br + 1);
            #pragma unroll
            for (int kx = 0; kx < 3; kx++) {
                int col = 5 + p + (kx - 1) * d;
                const uint4 v = tile[(ridx * 18 + col) * 4 + gg];
                s += __popc(v.z) + __popc(v.w);
            }
        }
        pzs[br][gg][p] = s;
    }
    __syncthreads();

    // ---- XNOR conv, 3 branches, fused RPReLU ----
    float outv[TW_];
    {
        float m2s = g_params[0][3][o] + g_params[1][3][o] + g_params[2][3][o];
        #pragma unroll
        for (int p = 0; p < TW_; p++) outv[p] = m2s;
    }

    const uint4* tg = tile + g;

    #pragma unroll
    for (int br = 0; br < 3; br++) {
        const int d = 2 * br + 1;
        const int rstep = br + 1;
        uint32_t wlo[9], whi[9];
        #pragma unroll
        for (int t = 0; t < 9; t++) {
            unsigned long long wq = g_wbits[br][t][o];
            wlo[t] = (uint32_t)wq;
            whi[t] = (uint32_t)(wq >> 32);
        }
        const float scl = g_params[br][0][o];
        const float c0  = g_params[br][1][o];
        const float al  = g_params[br][2][o];
        #pragma unroll
        for (int p = 0; p < TW_; p++) {
            // dot = pzs - 2 * sum_taps popc(nz & (s ^ w)); accumulate on fma pipe
            int acc = pzs[br][g][p];
            #pragma unroll
            for (int ky = 0; ky < 3; ky++) {
                const int ridx = 3 + (ky - 1) * rstep;
                #pragma unroll
                for (int kx = 0; kx < 3; kx++) {
                    const int col = 5 + p + (kx - 1) * d;
                    const uint4 v = tg[(ridx * 18 + col) * 4];
                    const int t = ky * 3 + kx;
                    imad_m2(acc, __popc(lop3_mask(v.z, v.x, wlo[t])));
                    imad_m2(acc, __popc(lop3_mask(v.w, v.y, whi[t])));
                }
            }
            float yv = scl * (float)acc + c0;
            yv = (yv >= 0.0f) ? yv : al * yv;      // RPReLU core
            outv[p] += yv;
        }
    }

    // ---- fused LayerNorm over channels ----
    #pragma unroll
    for (int p = 0; p < TW_; p++) redbuf[p][o] = outv[p];
    __syncthreads();
    {
        int wid = o >> 5, lane = o & 31;  // 8 warps, warp w reduces position w
        float s = 0.0f, sq = 0.0f;
        #pragma unroll
        for (int k = 0; k < 8; k++) {
            float v = redbuf[wid][lane + 32 * k];
            s += v; sq += v * v;
        }
        #pragma unroll
        for (int off = 16; off > 0; off >>= 1) {
            s  += __shfl_down_sync(0xFFFFFFFFu, s,  off);
            sq += __shfl_down_sync(0xFFFFFFFFu, sq, off);
        }
        if (lane == 0) {
            float mean = s * (1.0f / 256.0f);
            float var  = sq * (1.0f / 256.0f) - mean * mean;
            stats[wid][0] = mean;
            stats[wid][1] = rsqrtf(var + 1e-5f);
        }
    }
    __syncthreads();

    float gm = gamma[o], bt = beta[o];
    float res[TW_];
    #pragma unroll
    for (int p = 0; p < TW_; p++)
        res[p] = (outv[p] - stats[p][0]) * stats[p][1] * gm + bt;

    float4* op = (float4*)(out + (((size_t)b * C_ + o) * H_ + y) * W_ + x0);
    op[0] = make_float4(res[0], res[1], res[2], res[3]);
    op[1] = make_float4(res[4], res[5], res[6], res[7]);
}

// ---------------------------------------------------------------------------
extern "C" void kernel_launch(void* const* d_in, const int* in_sizes, int n_in,
                              void* d_out, int out_size) {
    const float* x     = (const float*)d_in[0];
    const float* bias  = (const float*)d_in[1];
    const float* w     = (const float*)d_in[2];
    const float* cb    = (const float*)d_in[3];
    const float* mv1   = (const float*)d_in[4];
    const float* alpha = (const float*)d_in[5];
    const float* mv2   = (const float*)d_in[6];
    const float* gamma = (const float*)d_in[7];
    const float* beta  = (const float*)d_in[8];
    float* out = (float*)d_out;

    pack_kernel<<<dim3(PH_, B_), 128>>>(x, bias);
    wprep_kernel<<<dim3(C_, 3), 64>>>(w, cb, mv1, alpha, mv2);
    main_kernel<<<dim3(W_ / TW_, H_, B_), 256>>>(gamma, beta, out);
}